// round 16
// baseline (speedup 1.0000x reference)
#include <cuda_runtime.h>
#include <cstdint>

#define N_NODES_MAX 100000
#define N_EDGES_MAX 1600000
#define D 128

// ---------------- scratch ----------------
__device__ float g_agg[(size_t)N_NODES_MAX * D];
__device__ int g_idx64;      // 1 if edge indices are int64, 0 if int32
__device__ int g_mask_mode;  // 0 = int32, 1 = uint8, 2 = float32
__device__ int g_hist[N_NODES_MAX];
__device__ int g_cursor[N_NODES_MAX];
__device__ int g_ssrc[N_EDGES_MAX];
__device__ int g_sdst[N_EDGES_MAX];

// ---------------- dtype detection ----------------
__global__ void detect_idx_kernel(const int* __restrict__ src_words) {
    __shared__ int any_nonzero;
    if (threadIdx.x == 0) any_nonzero = 0;
    __syncthreads();
    if (src_words[2 * threadIdx.x + 1] != 0) atomicOr(&any_nonzero, 1);
    __syncthreads();
    if (threadIdx.x == 0) g_idx64 = any_nonzero ? 0 : 1;
}

__global__ void detect_mask_kernel(const unsigned int* __restrict__ mw) {
    unsigned int w = mw[0];
    int mode = 0;
    if (w == 0x01010101u) mode = 1;
    else if (w == 0x3F800000u) mode = 2;
    g_mask_mode = mode;
}

__device__ __forceinline__ bool mask_active(const void* mask, int node) {
    int mm = g_mask_mode;
    if (mm == 1) return ((const unsigned char*)mask)[node] != 0;
    if (mm == 2) return ((const float*)mask)[node] != 0.0f;
    return ((const int*)mask)[node] != 0;
}

__device__ __forceinline__ int load_idx(const void* p, long long i) {
    return g_idx64 ? (int)((const long long*)p)[i] : ((const int*)p)[i];
}

// ---------------- zero agg + hist ----------------
__global__ void zero_agg_kernel(int n_elems4, int n_nodes) {
    int i = blockIdx.x * blockDim.x + threadIdx.x;
    int stride = gridDim.x * blockDim.x;
    float4 z = make_float4(0.f, 0.f, 0.f, 0.f);
    float4* p = reinterpret_cast<float4*>(g_agg);
    for (int j = i; j < n_elems4; j += stride) p[j] = z;
    for (int j = i; j < n_nodes; j += stride) g_hist[j] = 0;
}

// ---------------- counting sort by src: histogram ----------------
__global__ void hist_kernel(const void* __restrict__ src_idx, int n_edges) {
    int i = blockIdx.x * blockDim.x + threadIdx.x;
    if (i >= n_edges) return;
    atomicAdd(&g_hist[load_idx(src_idx, i)], 1);
}

// ---------------- exclusive scan of hist -> cursor (one block) ----------------
#define SCAN_T 1024
__global__ void __launch_bounds__(SCAN_T) scan_kernel(int n_nodes) {
    __shared__ int ps[SCAN_T];
    int t = threadIdx.x;
    int seg = (n_nodes + SCAN_T - 1) / SCAN_T;
    int s0 = t * seg;
    int s1 = s0 + seg; if (s1 > n_nodes) s1 = n_nodes;
    int sum = 0;
    for (int i = s0; i < s1; i++) sum += g_hist[i];
    ps[t] = sum;
    __syncthreads();
    // inclusive Hillis-Steele
    for (int off = 1; off < SCAN_T; off <<= 1) {
        int v = (t >= off) ? ps[t - off] : 0;
        __syncthreads();
        ps[t] += v;
        __syncthreads();
    }
    int run = ps[t] - sum;   // exclusive base for this segment
    for (int i = s0; i < s1; i++) {
        g_cursor[i] = run;
        run += g_hist[i];
    }
}

// ---------------- permute edges into src-sorted int32 arrays ----------------
__global__ void sortscatter_kernel(const void* __restrict__ src_idx,
                                   const void* __restrict__ dst_idx,
                                   int n_edges) {
    int i = blockIdx.x * blockDim.x + threadIdx.x;
    if (i >= n_edges) return;
    int s = load_idx(src_idx, i);
    int d = load_idx(dst_idx, i);
    int pos = atomicAdd(&g_cursor[s], 1);
    if (pos < N_EDGES_MAX) {
        g_ssrc[pos] = s;
        g_sdst[pos] = d;
    }
}

// ---------------- edge scatter on sorted edges: run-merged gathers ----------
#define EPW 8

__global__ void __launch_bounds__(256) scatter_kernel(
    const float* __restrict__ feat,
    int n_edges)
{
    int warp = (blockIdx.x * blockDim.x + threadIdx.x) >> 5;
    int lane = threadIdx.x & 31;
    long long e0 = (long long)warp * EPW;
    if (e0 >= n_edges) return;
    int cnt = n_edges - (int)e0;
    if (cnt > EPW) cnt = EPW;

    int s[EPW], d[EPW];
    #pragma unroll
    for (int i = 0; i < EPW; i++) {
        bool ok = i < cnt;
        s[i] = ok ? g_ssrc[e0 + i] : s[0];   // pad with s[0]: no extra gather
        d[i] = ok ? g_sdst[e0 + i] : -1;
    }

    const float4* f4 = reinterpret_cast<const float4*>(feat);
    float4 v[EPW];
    v[0] = f4[(size_t)s[0] * (D / 4) + lane];
    #pragma unroll
    for (int i = 1; i < EPW; i++) {
        if (s[i] == s[i - 1]) v[i] = v[i - 1];
        else                  v[i] = f4[(size_t)s[i] * (D / 4) + lane];
    }

    #pragma unroll
    for (int i = 0; i < EPW; i++) {
        if (d[i] >= 0) {
            float* dp = g_agg + (size_t)d[i] * D + lane * 4;
            asm volatile("red.global.add.v4.f32 [%0], {%1, %2, %3, %4};"
                         :: "l"(dp), "f"(v[i].x), "f"(v[i].y), "f"(v[i].z), "f"(v[i].w)
                         : "memory");
        }
    }
}

// ---------------- fused h build + norm + GEMM ----------------
// 512 threads, 64 nodes/block. Build: 8 threads per row, norm fused.
// GEMM: warp -> 4 nodes, lane -> 4 outs, k in steps of 4 (R5 known-good form).
#define NODES_PER_BLOCK 64
#define GEMM_THREADS 512
#define WT_PITCH 132   // 128 + 4 pad; multiple of 4 -> float4-aligned rows

__global__ void __launch_bounds__(GEMM_THREADS) norm_gemm_kernel(
    const float* __restrict__ feat,
    const void* __restrict__ mask,
    const float* __restrict__ W,
    const float* __restrict__ b,
    float* __restrict__ out,
    int n_nodes)
{
    extern __shared__ float smem[];
    float* Wt = smem;                                  // [128][WT_PITCH], Wt[k*P+o]
    float* Hs = Wt + D * WT_PITCH;                     // [64][128]
    float* inv_norm = Hs + NODES_PER_BLOCK * D;        // [64]

    const int tid = threadIdx.x;
    const int base = blockIdx.x * NODES_PER_BLOCK;

    // Load W (row-major [o][k]) -> transposed smem Wt[k][o]
    for (int idx = tid; idx < D * D; idx += GEMM_THREADS) {
        int o = idx >> 7;
        int k = idx & (D - 1);
        Wt[k * WT_PITCH + o] = W[idx];
    }

    // Build h tile with fused row sumsq: 8 threads per row.
    {
        int r = tid >> 3;          // 0..63
        int sub = tid & 7;
        int node = base + r;
        bool valid = node < n_nodes;
        bool act = valid && mask_active(mask, node);
        const float4* fr = reinterpret_cast<const float4*>(feat + (size_t)node * D);
        const float4* ar = reinterpret_cast<const float4*>(g_agg + (size_t)node * D);
        float ss = 0.f;
        #pragma unroll
        for (int j = 0; j < 4; j++) {
            int kc = sub * 4 + j * 32;   // float col index; per j the 8 subs cover 128B contiguous
            float4 v = make_float4(0.f, 0.f, 0.f, 0.f);
            if (valid) {
                v = fr[kc >> 2];
                if (act) {
                    float4 a = ar[kc >> 2];
                    v.x += a.x; v.y += a.y; v.z += a.z; v.w += a.w;
                }
            }
            ss += v.x * v.x + v.y * v.y + v.z * v.z + v.w * v.w;
            *reinterpret_cast<float4*>(Hs + r * D + kc) = v;
        }
        ss += __shfl_xor_sync(0xFFFFFFFFu, ss, 1);
        ss += __shfl_xor_sync(0xFFFFFFFFu, ss, 2);
        ss += __shfl_xor_sync(0xFFFFFFFFu, ss, 4);
        if (sub == 0) {
            float nrm = sqrtf(ss);
            inv_norm[r] = 1.0f / fmaxf(nrm, 1e-12f);
        }
    }
    __syncthreads();

    // GEMM micro-tile: warp -> 4 nodes, lane -> 4 outs, k in steps of 4.
    const int n0 = (tid >> 5) * 4;
    const int o0 = (tid & 31) * 4;

    float4 acc0 = make_float4(0.f, 0.f, 0.f, 0.f);
    float4 acc1 = acc0, acc2 = acc0, acc3 = acc0;

    const float4* h0 = reinterpret_cast<const float4*>(Hs + (n0 + 0) * D);
    const float4* h1 = reinterpret_cast<const float4*>(Hs + (n0 + 1) * D);
    const float4* h2 = reinterpret_cast<const float4*>(Hs + (n0 + 2) * D);
    const float4* h3 = reinterpret_cast<const float4*>(Hs + (n0 + 3) * D);

    #pragma unroll 4
    for (int kb = 0; kb < D / 4; kb++) {
        int k = kb * 4;
        float4 w0 = *reinterpret_cast<const float4*>(Wt + (k + 0) * WT_PITCH + o0);
        float4 w1 = *reinterpret_cast<const float4*>(Wt + (k + 1) * WT_PITCH + o0);
        float4 w2 = *reinterpret_cast<const float4*>(Wt + (k + 2) * WT_PITCH + o0);
        float4 w3 = *reinterpret_cast<const float4*>(Wt + (k + 3) * WT_PITCH + o0);
        float4 hA = h0[kb];
        float4 hB = h1[kb];
        float4 hC = h2[kb];
        float4 hD = h3[kb];

        acc0.x += hA.x*w0.x + hA.y*w1.x + hA.z*w2.x + hA.w*w3.x;
        acc0.y += hA.x*w0.y + hA.y*w1.y + hA.z*w2.y + hA.w*w3.y;
        acc0.z += hA.x*w0.z + hA.y*w1.z + hA.z*w2.z + hA.w*w3.z;
        acc0.w += hA.x*w0.w + hA.y*w1.w + hA.z*w2.w + hA.w*w3.w;

        acc1.x += hB.x*w0.x + hB.y*w1.x + hB.z*w2.x + hB.w*w3.x;
        acc1.y += hB.x*w0.y + hB.y*w1.y + hB.z*w2.y + hB.w*w3.y;
        acc1.z += hB.x*w0.z + hB.y*w1.z + hB.z*w2.z + hB.w*w3.z;
        acc1.w += hB.x*w0.w + hB.y*w1.w + hB.z*w2.w + hB.w*w3.w;

        acc2.x += hC.x*w0.x + hC.y*w1.x + hC.z*w2.x + hC.w*w3.x;
        acc2.y += hC.x*w0.y + hC.y*w1.y + hC.z*w2.y + hC.w*w3.y;
        acc2.z += hC.x*w0.z + hC.y*w1.z + hC.z*w2.z + hC.w*w3.z;
        acc2.w += hC.x*w0.w + hC.y*w1.w + hC.z*w2.w + hC.w*w3.w;

        acc3.x += hD.x*w0.x + hD.y*w1.x + hD.z*w2.x + hD.w*w3.x;
        acc3.y += hD.x*w0.y + hD.y*w1.y + hD.z*w2.y + hD.w*w3.y;
        acc3.z += hD.x*w0.z + hD.y*w1.z + hD.z*w2.z + hD.w*w3.z;
        acc3.w += hD.x*w0.w + hD.y*w1.w + hD.z*w2.w + hD.w*w3.w;
    }

    float4 bv = *reinterpret_cast<const float4*>(b + o0);
    float4 accs[4] = {acc0, acc1, acc2, acc3};
    #pragma unroll
    for (int i = 0; i < 4; i++) {
        int node = base + n0 + i;
        if (node >= n_nodes) break;
        float s = inv_norm[n0 + i];
        float4 r;
        r.x = accs[i].x * s + bv.x;
        r.y = accs[i].y * s + bv.y;
        r.z = accs[i].z * s + bv.z;
        r.w = accs[i].w * s + bv.w;
        *reinterpret_cast<float4*>(out + (size_t)node * D + o0) = r;
    }
}

// ---------------- launch ----------------
extern "C" void kernel_launch(void* const* d_in, const int* in_sizes, int n_in,
                              void* d_out, int out_size)
{
    const float* feat = (const float*)d_in[0];
    const void*  esrc = d_in[1];
    const void*  edst = d_in[2];
    const void*  mask = d_in[3];
    const float* W    = (const float*)d_in[4];
    const float* b    = (const float*)d_in[5];
    float*       out  = (float*)d_out;

    int n_nodes = in_sizes[0] / D;
    int n_edges = in_sizes[1];
    if (n_edges > N_EDGES_MAX) n_edges = N_EDGES_MAX;

    // 1. dtype detection
    detect_idx_kernel<<<1, 1024>>>((const int*)esrc);
    detect_mask_kernel<<<1, 1>>>((const unsigned int*)mask);

    // 2. zero agg + histogram bins
    int n4 = (n_nodes * D) / 4;
    zero_agg_kernel<<<2048, 256>>>(n4, n_nodes);

    // 3. counting sort of edges by src
    int eblocks = (n_edges + 255) / 256;
    hist_kernel<<<eblocks, 256>>>(esrc, n_edges);
    scan_kernel<<<1, SCAN_T>>>(n_nodes);
    sortscatter_kernel<<<eblocks, 256>>>(esrc, edst, n_edges);

    // 4. edge scatter on sorted edges (run-merged gathers)
    int n_warps = (n_edges + EPW - 1) / EPW;
    int sblocks = (n_warps + 7) / 8;
    scatter_kernel<<<sblocks, 256>>>(feat, n_edges);

    // 5. fused normalize + GEMM
    static bool attr_set = false;
    size_t smem_bytes = (D * WT_PITCH + NODES_PER_BLOCK * D + NODES_PER_BLOCK) * sizeof(float);
    if (!attr_set) {
        cudaFuncSetAttribute(norm_gemm_kernel,
                             cudaFuncAttributeMaxDynamicSharedMemorySize,
                             (int)smem_bytes);
        attr_set = true;
    }
    int gblocks = (n_nodes + NODES_PER_BLOCK - 1) / NODES_PER_BLOCK;
    norm_gemm_kernel<<<gblocks, GEMM_THREADS, smem_bytes>>>(feat, mask, W, b, out, n_nodes);
}